// round 7
// baseline (speedup 1.0000x reference)
#include <cuda_runtime.h>
#include <cstdint>

#define NBINS  31
#define NEDGES 32
#define FLT_BIG 3.402823466e38f

// ---------------- device-global accumulators (re-initialized every launch) ----
__device__ double              g_sum;
__device__ double              g_ss;
__device__ unsigned long long  g_nz;
__device__ unsigned int        g_minkey;
__device__ unsigned int        g_maxkey;
__device__ int                 g_hist[NBINS];
__device__ float               g_edges[NEDGES];
__device__ float               g_mn, g_mx, g_scale, g_bias;

// order-preserving float <-> uint key
__device__ __forceinline__ unsigned int fkey(float f) {
    unsigned int u = __float_as_uint(f);
    return (u & 0x80000000u) ? ~u : (u | 0x80000000u);
}
__device__ __forceinline__ float keyf(unsigned int k) {
    unsigned int u = (k & 0x80000000u) ? (k ^ 0x80000000u) : ~k;
    return __uint_as_float(u);
}

// ---------------- kernel 0: reset accumulators ------------------------------
__global__ void init_kernel() {
    int t = threadIdx.x;
    if (t == 0) {
        g_sum = 0.0; g_ss = 0.0; g_nz = 0ull;
        g_minkey = 0xFFFFFFFFu; g_maxkey = 0u;
    }
    if (t < NBINS) g_hist[t] = 0;
}

// ---------------- kernel 1: min/max/sum/ss/nonzero --------------------------
__global__ void __launch_bounds__(256) stats_kernel(const float* __restrict__ xf, long long n) {
    const float4* __restrict__ x = (const float4*)xf;
    int nvec  = (int)(n >> 2);
    int total = gridDim.x * blockDim.x;
    int i0    = blockIdx.x * blockDim.x + threadIdx.x;

    float lmin = FLT_BIG, lmax = -FLT_BIG;
    float lsum = 0.0f, lss = 0.0f;
    int   lnz  = 0;

    for (int i = i0; i < nvec; i += total) {
        float4 v = x[i];
        lsum += v.x; lss = fmaf(v.x, v.x, lss);
        lmin = fminf(lmin, v.x); lmax = fmaxf(lmax, v.x); lnz += (v.x != 0.0f);
        lsum += v.y; lss = fmaf(v.y, v.y, lss);
        lmin = fminf(lmin, v.y); lmax = fmaxf(lmax, v.y); lnz += (v.y != 0.0f);
        lsum += v.z; lss = fmaf(v.z, v.z, lss);
        lmin = fminf(lmin, v.z); lmax = fmaxf(lmax, v.z); lnz += (v.z != 0.0f);
        lsum += v.w; lss = fmaf(v.w, v.w, lss);
        lmin = fminf(lmin, v.w); lmax = fmaxf(lmax, v.w); lnz += (v.w != 0.0f);
    }
    // scalar tail (empty for N % 4 == 0)
    for (long long i = ((long long)nvec << 2) + i0; i < n; i += total) {
        float v = xf[i];
        lsum += v; lss = fmaf(v, v, lss);
        lmin = fminf(lmin, v); lmax = fmaxf(lmax, v); lnz += (v != 0.0f);
    }

    // warp reduce
    #pragma unroll
    for (int o = 16; o; o >>= 1) {
        lsum += __shfl_down_sync(0xFFFFFFFFu, lsum, o);
        lss  += __shfl_down_sync(0xFFFFFFFFu, lss,  o);
        lmin  = fminf(lmin, __shfl_down_sync(0xFFFFFFFFu, lmin, o));
        lmax  = fmaxf(lmax, __shfl_down_sync(0xFFFFFFFFu, lmax, o));
        lnz  += __shfl_down_sync(0xFFFFFFFFu, lnz,  o);
    }

    __shared__ float s_sum[8], s_ss[8], s_min[8], s_max[8];
    __shared__ int   s_nz[8];
    int w = threadIdx.x >> 5, lane = threadIdx.x & 31;
    if (lane == 0) { s_sum[w] = lsum; s_ss[w] = lss; s_min[w] = lmin; s_max[w] = lmax; s_nz[w] = lnz; }
    __syncthreads();

    if (threadIdx.x == 0) {
        double bs = 0.0, bss = 0.0;
        float bmin = FLT_BIG, bmax = -FLT_BIG;
        unsigned long long bnz = 0ull;
        #pragma unroll
        for (int k = 0; k < 8; ++k) {
            bs += (double)s_sum[k]; bss += (double)s_ss[k];
            bmin = fminf(bmin, s_min[k]); bmax = fmaxf(bmax, s_max[k]);
            bnz += (unsigned long long)s_nz[k];
        }
        atomicAdd(&g_sum, bs);
        atomicAdd(&g_ss, bss);
        atomicAdd(&g_nz, bnz);
        atomicMin(&g_minkey, fkey(bmin));
        atomicMax(&g_maxkey, fkey(bmax));
    }
}

// ---------------- kernel 2: compute edges / scale ---------------------------
__global__ void prep_kernel() {
    int t = threadIdx.x;
    float mn = keyf(g_minkey);
    float mx = keyf(g_maxkey);
    float step = (mx - mn) / (float)NBINS;
    if (t == 0) {
        g_mn = mn; g_mx = mx;
        float inv = (float)NBINS / (mx - mn);
        g_scale = inv;
        g_bias  = -mn * inv;
    }
    if (t < NEDGES) g_edges[t] = (t == NBINS) ? mx : fmaf((float)t, step, mn);
}

// ---------------- kernel 3: histogram ---------------------------------------
__device__ __forceinline__ int bin_index(float xc, float scale, float bias,
                                         const float* __restrict__ se) {
    float f = fmaf(xc, scale, bias);
    int idx = (int)f;                       // trunc toward zero
    idx = idx < 0 ? 0 : (idx > NBINS - 1 ? NBINS - 1 : idx);
    float fr = f - (float)idx;
    if (fr < 2e-4f || fr > 1.0f - 2e-4f) {  // near an edge -> exact searchsorted semantics
        while (idx > 0 && xc < se[idx]) --idx;
        while (idx < NBINS - 1 && xc >= se[idx + 1]) ++idx;
    }
    return idx;
}

__device__ __forceinline__ void hist_one(float xc, float scale, float bias,
                                         const float* __restrict__ se,
                                         int* __restrict__ myrow, int lane) {
    int idx = bin_index(xc, scale, bias, se);
    unsigned m = __match_any_sync(0xFFFFFFFFu, idx);
    int leader = __ffs(m) - 1;
    if (lane == leader) myrow[idx] += __popc(m);   // warp-private row, no atomic needed
}

__global__ void __launch_bounds__(256) hist_kernel(const float* __restrict__ xf, long long n) {
    const float4* __restrict__ x = (const float4*)xf;
    int nvec  = (int)(n >> 2);
    int total = gridDim.x * blockDim.x;
    int i0    = blockIdx.x * blockDim.x + threadIdx.x;
    int t     = threadIdx.x;
    int w     = t >> 5, lane = t & 31;

    __shared__ float se[NEDGES];
    __shared__ int   sh[8 * 32];
    if (t < NEDGES) se[t] = g_edges[t];
    sh[t] = 0;                                     // 256 == 8*32
    __syncthreads();

    float scale = g_scale;
    float bias  = g_bias;
    int* myrow  = &sh[w * 32];

    // Full uniform iterations (all 32 lanes active -> match_any legal).
    // Iterate in REVERSE so we harvest the L2-resident tail left by stats_kernel.
    int K = nvec / total;
    for (int k = K - 1; k >= 0; --k) {
        float4 v = x[i0 + k * total];
        hist_one(v.x, scale, bias, se, myrow, lane);
        hist_one(v.y, scale, bias, se, myrow, lane);
        hist_one(v.z, scale, bias, se, myrow, lane);
        hist_one(v.w, scale, bias, se, myrow, lane);
    }
    // vector tail (possibly partial warp -> atomic path)
    int ti = K * total + i0;
    if (ti < nvec) {
        float4 v = x[ti];
        atomicAdd(&myrow[bin_index(v.x, scale, bias, se)], 1);
        atomicAdd(&myrow[bin_index(v.y, scale, bias, se)], 1);
        atomicAdd(&myrow[bin_index(v.z, scale, bias, se)], 1);
        atomicAdd(&myrow[bin_index(v.w, scale, bias, se)], 1);
    }
    // scalar tail
    for (long long si = ((long long)nvec << 2) + i0; si < n; si += total) {
        atomicAdd(&myrow[bin_index(xf[si], scale, bias, se)], 1);
    }

    __syncthreads();
    if (t < NBINS) {
        int s = 0;
        #pragma unroll
        for (int ww = 0; ww < 8; ++ww) s += sh[ww * 32 + t];
        atomicAdd(&g_hist[t], s);
    }
}

// ---------------- kernel 4: write the 69 outputs ----------------------------
__global__ void finalize_kernel(float* __restrict__ out, long long n) {
    int t = threadIdx.x;
    if (t == 0) {
        out[0] = g_mn;
        out[1] = g_mx;
        out[2] = (float)n;                 // num
        out[3] = (float)g_nz;              // nonzero count
        out[4] = (float)g_sum;             // sum
        out[5] = (float)g_ss;              // sum of squares
    }
    if (t < NBINS)  out[6 + t]          = (float)g_hist[t];
    if (t < NEDGES) out[6 + NBINS + t]  = g_edges[t];
}

// ---------------- launch ----------------------------------------------------
extern "C" void kernel_launch(void* const* d_in, const int* in_sizes, int n_in,
                              void* d_out, int out_size) {
    const float* x = (const float*)d_in[0];
    long long n = (long long)in_sizes[0];
    float* out = (float*)d_out;

    const int BLOCKS = 2048, THREADS = 256;

    init_kernel<<<1, 32>>>();
    stats_kernel<<<BLOCKS, THREADS>>>(x, n);
    prep_kernel<<<1, 32>>>();
    hist_kernel<<<BLOCKS, THREADS>>>(x, n);
    finalize_kernel<<<1, 64>>>(out, n);
}

// round 8
// speedup vs baseline: 2.4558x; 2.4558x over previous
#include <cuda_runtime.h>
#include <cstdint>

#define NBINS  31
#define NEDGES 32
#define FLT_BIG 3.402823466e38f

// ---------------- device-global accumulators (re-initialized every launch) ----
__device__ double              g_sum;
__device__ double              g_ss;
__device__ unsigned long long  g_nz;
__device__ unsigned int        g_minkey;
__device__ unsigned int        g_maxkey;
__device__ int                 g_hist[NBINS];
__device__ float               g_edges[NEDGES];
__device__ float               g_mn, g_mx, g_scale, g_bias;

// order-preserving float <-> uint key
__device__ __forceinline__ unsigned int fkey(float f) {
    unsigned int u = __float_as_uint(f);
    return (u & 0x80000000u) ? ~u : (u | 0x80000000u);
}
__device__ __forceinline__ float keyf(unsigned int k) {
    unsigned int u = (k & 0x80000000u) ? (k ^ 0x80000000u) : ~k;
    return __uint_as_float(u);
}

// ---------------- kernel 0: reset accumulators ------------------------------
__global__ void init_kernel() {
    int t = threadIdx.x;
    if (t == 0) {
        g_sum = 0.0; g_ss = 0.0; g_nz = 0ull;
        g_minkey = 0xFFFFFFFFu; g_maxkey = 0u;
    }
    if (t < NBINS) g_hist[t] = 0;
}

// ---------------- kernel 1: min/max/sum/ss/nonzero --------------------------
__global__ void __launch_bounds__(256) stats_kernel(const float* __restrict__ xf, long long n) {
    const float4* __restrict__ x = (const float4*)xf;
    int nvec  = (int)(n >> 2);
    int total = gridDim.x * blockDim.x;
    int i0    = blockIdx.x * blockDim.x + threadIdx.x;

    float lmin = FLT_BIG, lmax = -FLT_BIG;
    float lsum = 0.0f, lss = 0.0f;
    int   lnz  = 0;

    #pragma unroll 4
    for (int i = i0; i < nvec; i += total) {
        float4 v = x[i];
        lsum += v.x; lss = fmaf(v.x, v.x, lss);
        lmin = fminf(lmin, v.x); lmax = fmaxf(lmax, v.x); lnz += (v.x != 0.0f);
        lsum += v.y; lss = fmaf(v.y, v.y, lss);
        lmin = fminf(lmin, v.y); lmax = fmaxf(lmax, v.y); lnz += (v.y != 0.0f);
        lsum += v.z; lss = fmaf(v.z, v.z, lss);
        lmin = fminf(lmin, v.z); lmax = fmaxf(lmax, v.z); lnz += (v.z != 0.0f);
        lsum += v.w; lss = fmaf(v.w, v.w, lss);
        lmin = fminf(lmin, v.w); lmax = fmaxf(lmax, v.w); lnz += (v.w != 0.0f);
    }
    // scalar tail (empty for N % 4 == 0)
    for (long long i = ((long long)nvec << 2) + i0; i < n; i += total) {
        float v = xf[i];
        lsum += v; lss = fmaf(v, v, lss);
        lmin = fminf(lmin, v); lmax = fmaxf(lmax, v); lnz += (v != 0.0f);
    }

    // warp reduce
    #pragma unroll
    for (int o = 16; o; o >>= 1) {
        lsum += __shfl_down_sync(0xFFFFFFFFu, lsum, o);
        lss  += __shfl_down_sync(0xFFFFFFFFu, lss,  o);
        lmin  = fminf(lmin, __shfl_down_sync(0xFFFFFFFFu, lmin, o));
        lmax  = fmaxf(lmax, __shfl_down_sync(0xFFFFFFFFu, lmax, o));
        lnz  += __shfl_down_sync(0xFFFFFFFFu, lnz,  o);
    }

    __shared__ float s_sum[8], s_ss[8], s_min[8], s_max[8];
    __shared__ int   s_nz[8];
    int w = threadIdx.x >> 5, lane = threadIdx.x & 31;
    if (lane == 0) { s_sum[w] = lsum; s_ss[w] = lss; s_min[w] = lmin; s_max[w] = lmax; s_nz[w] = lnz; }
    __syncthreads();

    if (threadIdx.x == 0) {
        double bs = 0.0, bss = 0.0;
        float bmin = FLT_BIG, bmax = -FLT_BIG;
        unsigned long long bnz = 0ull;
        #pragma unroll
        for (int k = 0; k < 8; ++k) {
            bs += (double)s_sum[k]; bss += (double)s_ss[k];
            bmin = fminf(bmin, s_min[k]); bmax = fmaxf(bmax, s_max[k]);
            bnz += (unsigned long long)s_nz[k];
        }
        atomicAdd(&g_sum, bs);
        atomicAdd(&g_ss, bss);
        atomicAdd(&g_nz, bnz);
        atomicMin(&g_minkey, fkey(bmin));
        atomicMax(&g_maxkey, fkey(bmax));
    }
}

// ---------------- kernel 2: compute edges / scale ---------------------------
__global__ void prep_kernel() {
    int t = threadIdx.x;
    float mn = keyf(g_minkey);
    float mx = keyf(g_maxkey);
    float step = (mx - mn) / (float)NBINS;
    if (t == 0) {
        g_mn = mn; g_mx = mx;
        float inv = (float)NBINS / (mx - mn);
        g_scale = inv;
        g_bias  = -mn * inv;
    }
    if (t < NEDGES) g_edges[t] = (t == NBINS) ? mx : fmaf((float)t, step, mn);
}

// ---------------- kernel 3: histogram ---------------------------------------
// Exact searchsorted(edges, x, 'right')-1 semantics. The fma-based index is
// off by at most 1, and only when f lands within EPS of an integer; only then
// do we consult the exact edge array.
__device__ __forceinline__ int bin_of(float xc, float scale, float bias,
                                      const float* __restrict__ se) {
    float f = fmaf(xc, scale, bias);       // >= ~0 (tiny negative possible at x==mn)
    int i = (int)f;                        // trunc toward zero -> 0 for tiny negatives
    i = i > NBINS - 1 ? NBINS - 1 : i;
    float r = f - (float)i;
    if (r < 5e-4f || r > 1.0f - 5e-4f) {   // rare: near an edge -> exact comparison
        if (xc < se[i])            i -= 1;
        else if (xc >= se[i + 1])  i += 1; // se[31]==mx: x==mx -> 31, clamped below
        i = i < 0 ? 0 : (i > NBINS - 1 ? NBINS - 1 : i);
    }
    return i;
}

__global__ void __launch_bounds__(256) hist_kernel(const float* __restrict__ xf, long long n) {
    // Per-thread byte counters: word index = bin*256 + tid, the 4 bytes of the
    // word are the 4 sub-rows (one per float4 component). Bank of every access
    // = lane -> conflict-free for any bin pattern.
    __shared__ unsigned int cnt[NBINS * 256];    // 31744 B
    __shared__ float se[NEDGES];
    __shared__ int   bsum[NBINS];

    int t = threadIdx.x;
    #pragma unroll
    for (int b = 0; b < NBINS; ++b) cnt[b * 256 + t] = 0u;
    if (t < NEDGES) se[t] = g_edges[t];
    if (t < NBINS)  bsum[t] = 0;
    __syncthreads();

    float scale = g_scale;
    float bias  = g_bias;

    const float4* __restrict__ x4 = (const float4*)xf;
    int nvec  = (int)(n >> 2);
    int total = gridDim.x * blockDim.x;
    int i0    = blockIdx.x * blockDim.x + t;

    unsigned char* c8 = (unsigned char*)cnt;
    int base = t * 4;

    // Reverse order: harvest the L2-resident tail left by stats_kernel.
    // Manual 2x unroll so both LDG.128 issue before the counter chains.
    int K = nvec / total;
    int k = K;
    for (; k >= 2; k -= 2) {
        float4 a = x4[i0 + (k - 1) * total];
        float4 b = x4[i0 + (k - 2) * total];
        c8[bin_of(a.x, scale, bias, se) * 1024 + base + 0]++;
        c8[bin_of(a.y, scale, bias, se) * 1024 + base + 1]++;
        c8[bin_of(a.z, scale, bias, se) * 1024 + base + 2]++;
        c8[bin_of(a.w, scale, bias, se) * 1024 + base + 3]++;
        c8[bin_of(b.x, scale, bias, se) * 1024 + base + 0]++;
        c8[bin_of(b.y, scale, bias, se) * 1024 + base + 1]++;
        c8[bin_of(b.z, scale, bias, se) * 1024 + base + 2]++;
        c8[bin_of(b.w, scale, bias, se) * 1024 + base + 3]++;
    }
    if (k == 1) {
        float4 a = x4[i0];
        c8[bin_of(a.x, scale, bias, se) * 1024 + base + 0]++;
        c8[bin_of(a.y, scale, bias, se) * 1024 + base + 1]++;
        c8[bin_of(a.z, scale, bias, se) * 1024 + base + 2]++;
        c8[bin_of(a.w, scale, bias, se) * 1024 + base + 3]++;
    }
    // vector tail (partial stride) — per-thread rows, no atomics needed
    {
        int ti = K * total + i0;
        if (ti < nvec) {
            float4 a = x4[ti];
            c8[bin_of(a.x, scale, bias, se) * 1024 + base + 0]++;
            c8[bin_of(a.y, scale, bias, se) * 1024 + base + 1]++;
            c8[bin_of(a.z, scale, bias, se) * 1024 + base + 2]++;
            c8[bin_of(a.w, scale, bias, se) * 1024 + base + 3]++;
        }
    }
    // scalar tail
    for (long long si = ((long long)nvec << 2) + i0; si < n; si += total)
        c8[bin_of(xf[si], scale, bias, se) * 1024 + base]++;

    __syncthreads();

    // Block reduce: 8 threads per bin, each sums 32 words via dp4a.
    // Rotated index ((j + t) & 31) keeps the 32 lanes on distinct banks.
    if (t < NBINS * 8) {
        int b = t >> 3, seg = t & 7;
        unsigned int acc = 0;
        #pragma unroll
        for (int j = 0; j < 32; ++j) {
            unsigned int w = cnt[b * 256 + seg * 32 + ((j + t) & 31)];
            acc = __dp4a(w, 0x01010101u, acc);
        }
        atomicAdd(&bsum[b], (int)acc);
    }
    __syncthreads();
    if (t < NBINS) atomicAdd(&g_hist[t], bsum[t]);
}

// ---------------- kernel 4: write the 69 outputs ----------------------------
__global__ void finalize_kernel(float* __restrict__ out, long long n) {
    int t = threadIdx.x;
    if (t == 0) {
        out[0] = g_mn;
        out[1] = g_mx;
        out[2] = (float)n;                 // num
        out[3] = (float)g_nz;              // nonzero count
        out[4] = (float)g_sum;             // sum
        out[5] = (float)g_ss;              // sum of squares
    }
    if (t < NBINS)  out[6 + t]          = (float)g_hist[t];
    if (t < NEDGES) out[6 + NBINS + t]  = g_edges[t];
}

// ---------------- launch ----------------------------------------------------
extern "C" void kernel_launch(void* const* d_in, const int* in_sizes, int n_in,
                              void* d_out, int out_size) {
    const float* x = (const float*)d_in[0];
    long long n = (long long)in_sizes[0];
    float* out = (float*)d_out;

    init_kernel<<<1, 32>>>();
    stats_kernel<<<2048, 256>>>(x, n);          // no smem pressure -> wide grid
    prep_kernel<<<1, 32>>>();
    hist_kernel<<<1024, 256>>>(x, n);           // 32KB smem -> ~7 CTAs/SM, 1 wave
    finalize_kernel<<<1, 64>>>(out, n);
}